// round 1
// baseline (speedup 1.0000x reference)
#include <cuda_runtime.h>
#include <math.h>

#define Bdim   64
#define Ndim   1024
#define H16d   256
#define H64d   1024
#define H128d  2048
#define G4d    8192   // 4*H128

// ---------------- scratch (device globals; no allocations allowed) ----------
__device__ float g_gcn[Bdim * Ndim];     // GCN output          (64,1024)
__device__ float g_f  [Bdim * H16d];     // relu(first layer)   (64,256)
__device__ float g_i  [Bdim * H64d];     // relu(inter layer)   (64,1024)
__device__ float g_z  [Bdim * H128d];    // relu(out layer)     (64,2048)
__device__ float g_gih[Bdim * G4d];      // z@w_ih^T + b_ih + b_hh (64,8192)
__device__ float g_h  [2][H128d];        // ping-pong hidden state
__device__ float g_c  [H128d];           // cell state

// ---------------------------------------------------------------------------
// Stage 1: GCN per row. One block per row, 1024 threads.
//   d[i][j] = |x_i - x_j| (diag = inf); idx = 4 smallest (ties -> lower j)
//   S_i = sum_k x[idx[i][k]]
//   s2[i] = sum_c relu(S_i*w1[c]+b1[c]) * w2[c]
//   out[i] = sum_k s2[idx[i][k]] + b2
// ---------------------------------------------------------------------------
__global__ __launch_bounds__(Ndim)
void gcn_kernel(const float* __restrict__ inp,
                const float* __restrict__ w1, const float* __restrict__ b1,
                const float* __restrict__ w2, const float* __restrict__ b2)
{
    __shared__ float xs[Ndim];
    __shared__ float s2[Ndim];
    const int i   = threadIdx.x;
    const int row = blockIdx.x;

    const float xi = inp[row * Ndim + i];
    xs[i] = xi;
    __syncthreads();

    float d0 = INFINITY, d1 = INFINITY, d2 = INFINITY, d3 = INFINITY;
    int   j0 = 0, j1 = 0, j2 = 0, j3 = 0;

    #pragma unroll 4
    for (int j = 0; j < Ndim; j++) {
        float d = fabsf(xi - xs[j]);
        if (j != i && d < d3) {
            if (d < d2) {
                d3 = d2; j3 = j2;
                if (d < d1) {
                    d2 = d1; j2 = j1;
                    if (d < d0) { d1 = d0; j1 = j0; d0 = d; j0 = j; }
                    else        { d1 = d;  j1 = j; }
                } else { d2 = d; j2 = j; }
            } else { d3 = d; j3 = j; }
        }
    }

    const float S = xs[j0] + xs[j1] + xs[j2] + xs[j3];

    float acc = 0.f;
    #pragma unroll
    for (int c = 0; c < 4; c++) {
        float h = fmaxf(S * w1[c] + b1[c], 0.f);
        acc += h * w2[c];
    }
    s2[i] = acc;
    __syncthreads();

    g_gcn[row * Ndim + i] = s2[j0] + s2[j1] + s2[j2] + s2[j3] + b2[0];
}

// ---------------------------------------------------------------------------
// Stage 2a: first layer (K=1024, N=256): warp-per-output dot kernel.
//   g_f[m][n] = relu( g_gcn[m,:] . fl_w[n,:] + fl_b[n] )
// ---------------------------------------------------------------------------
__global__ __launch_bounds__(256)
void fc1_kernel(const float* __restrict__ W, const float* __restrict__ bias)
{
    const int gw   = (blockIdx.x * blockDim.x + threadIdx.x) >> 5;
    const int lane = threadIdx.x & 31;
    const int m = gw >> 8;      // / 256
    const int n = gw & 255;

    const float4* ar = (const float4*)(g_gcn + m * Ndim);
    const float4* wr = (const float4*)(W     + n * Ndim);

    float a = 0.f;
    #pragma unroll
    for (int it = 0; it < 8; it++) {
        float4 av = ar[it * 32 + lane];
        float4 wv = wr[it * 32 + lane];
        a += av.x * wv.x + av.y * wv.y + av.z * wv.z + av.w * wv.w;
    }
    #pragma unroll
    for (int off = 16; off; off >>= 1)
        a += __shfl_down_sync(0xffffffffu, a, off);

    if (lane == 0)
        g_f[m * H16d + n] = fmaxf(a + bias[n], 0.f);
}

// ---------------------------------------------------------------------------
// Generic M=64 tiled SGEMM:  C[m][n] = act( A[m,:K] . W[n,:K] + bias[n] (+bias2[n]) )
// Block: 64 output columns, all 64 rows. 256 threads, 4x4 micro-tiles, BK=16.
// ---------------------------------------------------------------------------
template<int K, bool RELU>
__global__ __launch_bounds__(256)
void gemm64_kernel(const float* __restrict__ A, const float* __restrict__ W,
                   const float* __restrict__ bias, const float* __restrict__ bias2,
                   float* __restrict__ C, int Ncols)
{
    __shared__ float As[16][65];
    __shared__ float Ws[16][65];

    const int tid = threadIdx.x;
    const int tx  = tid & 15;        // n-dim
    const int ty  = tid >> 4;        // m-dim
    const int nb  = blockIdx.x * 64;

    const int lm = tid >> 2;         // 0..63: row of staged tile
    const int lk = (tid & 3) << 2;   // 0,4,8,12

    float acc[4][4];
    #pragma unroll
    for (int a = 0; a < 4; a++)
        #pragma unroll
        for (int b = 0; b < 4; b++) acc[a][b] = 0.f;

    for (int kc = 0; kc < K; kc += 16) {
        float4 a4 = *(const float4*)(A + (size_t)lm * K + kc + lk);
        float4 w4 = *(const float4*)(W + (size_t)(nb + lm) * K + kc + lk);
        As[lk + 0][lm] = a4.x; As[lk + 1][lm] = a4.y;
        As[lk + 2][lm] = a4.z; As[lk + 3][lm] = a4.w;
        Ws[lk + 0][lm] = w4.x; Ws[lk + 1][lm] = w4.y;
        Ws[lk + 2][lm] = w4.z; Ws[lk + 3][lm] = w4.w;
        __syncthreads();

        #pragma unroll
        for (int kk = 0; kk < 16; kk++) {
            float av[4], wv[4];
            #pragma unroll
            for (int a = 0; a < 4; a++) av[a] = As[kk][ty * 4 + a];
            #pragma unroll
            for (int b = 0; b < 4; b++) wv[b] = Ws[kk][tx * 4 + b];
            #pragma unroll
            for (int a = 0; a < 4; a++)
                #pragma unroll
                for (int b = 0; b < 4; b++)
                    acc[a][b] += av[a] * wv[b];
        }
        __syncthreads();
    }

    #pragma unroll
    for (int a = 0; a < 4; a++) {
        const int m = ty * 4 + a;
        #pragma unroll
        for (int b = 0; b < 4; b++) {
            const int n = nb + tx * 4 + b;
            float v = acc[a][b] + bias[n];
            if (bias2) v += bias2[n];
            if (RELU)  v = fmaxf(v, 0.f);
            C[(size_t)m * Ncols + n] = v;
        }
    }
}

// ---------------------------------------------------------------------------
// LSTM state init
// ---------------------------------------------------------------------------
__global__ void init_state_kernel()
{
    int t = blockIdx.x * blockDim.x + threadIdx.x;
    if (t < H128d) { g_h[0][t] = 0.f; g_c[t] = 0.f; }
}

// ---------------------------------------------------------------------------
// One LSTM step. Grid 256 blocks x 256 threads. Block b owns hidden units
// j in [8b, 8b+8); warp w computes the 4 gate rows (g*2048 + j) for j = 8b+w.
// h_prev staged in smem; w_hh streamed (L2-resident after step 0).
// ---------------------------------------------------------------------------
__global__ __launch_bounds__(256)
void lstm_step_kernel(const float* __restrict__ whh, int t, int sel,
                      float* __restrict__ out)
{
    __shared__ float hsm[H128d];

    const int tid = threadIdx.x;
    // stage h_prev (2048 floats = 512 float4)
    {
        const float4* hp = (const float4*)g_h[sel];
        float4* hs4 = (float4*)hsm;
        hs4[tid]       = hp[tid];
        hs4[tid + 256] = hp[tid + 256];
    }
    __syncthreads();

    const int lane = tid & 31;
    const int w    = tid >> 5;
    const int j    = blockIdx.x * 8 + w;

    float acc[4] = {0.f, 0.f, 0.f, 0.f};
    const float4* hs4 = (const float4*)hsm;

    #pragma unroll
    for (int g = 0; g < 4; g++) {
        const float4* wrow = (const float4*)(whh + (size_t)(g * H128d + j) * H128d);
        float a = 0.f;
        #pragma unroll
        for (int it = 0; it < 16; it++) {
            float4 wv = wrow[it * 32 + lane];
            float4 hv = hs4 [it * 32 + lane];
            a += wv.x * hv.x + wv.y * hv.y + wv.z * hv.z + wv.w * hv.w;
        }
        acc[g] = a;
    }

    #pragma unroll
    for (int off = 16; off; off >>= 1) {
        #pragma unroll
        for (int g = 0; g < 4; g++)
            acc[g] += __shfl_down_sync(0xffffffffu, acc[g], off);
    }

    if (lane == 0) {
        const float* gih = g_gih + (size_t)t * G4d;
        float ig = acc[0] + gih[j];
        float fg = acc[1] + gih[H128d     + j];
        float gg = acc[2] + gih[2 * H128d + j];
        float og = acc[3] + gih[3 * H128d + j];

        float si = 1.f / (1.f + __expf(-ig));
        float sf = 1.f / (1.f + __expf(-fg));
        float so = 1.f / (1.f + __expf(-og));

        float cn = sf * g_c[j] + si * tanhf(gg);
        float hn = so * tanhf(cn);

        g_c[j]          = cn;
        g_h[sel ^ 1][j] = hn;
        out[(size_t)t * H128d + j] = hn;
    }
}

// ---------------------------------------------------------------------------
extern "C" void kernel_launch(void* const* d_in, const int* in_sizes, int n_in,
                              void* d_out, int out_size)
{
    const float* input = (const float*)d_in[0];
    // d_in[1] Hidden_State, d_in[2] Cell_State: unused (reference uses zeros)
    const float* gc1_w = (const float*)d_in[3];
    const float* gc1_b = (const float*)d_in[4];
    const float* gc2_w = (const float*)d_in[5];
    const float* gc2_b = (const float*)d_in[6];
    const float* fl_w  = (const float*)d_in[7];
    const float* fl_b  = (const float*)d_in[8];
    const float* il_w  = (const float*)d_in[9];
    const float* il_b  = (const float*)d_in[10];
    const float* ol_w  = (const float*)d_in[11];
    const float* ol_b  = (const float*)d_in[12];
    const float* w_ih  = (const float*)d_in[13];
    const float* w_hh  = (const float*)d_in[14];
    const float* b_ih  = (const float*)d_in[15];
    const float* b_hh  = (const float*)d_in[16];
    float* out = (float*)d_out;

    float *p_f, *p_i, *p_z, *p_gih;
    cudaGetSymbolAddress((void**)&p_f,   g_f);
    cudaGetSymbolAddress((void**)&p_i,   g_i);
    cudaGetSymbolAddress((void**)&p_z,   g_z);
    cudaGetSymbolAddress((void**)&p_gih, g_gih);

    // Stage 1: GCN
    gcn_kernel<<<Bdim, Ndim>>>(input, gc1_w, gc1_b, gc2_w, gc2_b);

    // Stage 2: MLP chain + input projection (biases folded, relu fused)
    fc1_kernel<<<(Bdim * H16d) / 8, 256>>>(fl_w, fl_b);
    gemm64_kernel<H16d,  true ><<<H64d  / 64, 256>>>(p_f, il_w, il_b, nullptr, p_i,  H64d);
    gemm64_kernel<H64d,  true ><<<H128d / 64, 256>>>(p_i, ol_w, ol_b, nullptr, p_z,  H128d);
    gemm64_kernel<H128d, false><<<G4d   / 64, 256>>>(p_z, w_ih, b_ih, b_hh,    p_gih, G4d);

    // Stage 3: LSTM scan (64 sequential steps)
    init_state_kernel<<<8, 256>>>();
    int sel = 0;
    for (int t = 0; t < Bdim; t++) {
        lstm_step_kernel<<<256, 256>>>(w_hh, t, sel, out);
        sel ^= 1;
    }
}

// round 3
// speedup vs baseline: 1.1309x; 1.1309x over previous
#include <cuda_runtime.h>
#include <math.h>

#define Bdim   64
#define Ndim   1024
#define H16d   256
#define H64d   1024
#define H128d  2048
#define G4d    8192   // 4*H128

#define CACHED 27     // w_hh rows cached in smem per block (27*8KB = 216KB)

// ---------------- scratch (device globals; no allocations allowed) ----------
__device__ float g_gcn[Bdim * Ndim];     // GCN output          (64,1024)
__device__ float g_f  [Bdim * H16d];     // relu(first layer)   (64,256)
__device__ float g_i  [Bdim * H64d];     // relu(inter layer)   (64,1024)
__device__ float g_z  [Bdim * H128d];    // relu(out layer)     (64,2048)
__device__ float g_gih[Bdim * G4d];      // z@w_ih^T + b_ih + b_hh (64,8192)
__device__ unsigned g_bar;               // grid barrier counter

// ---------------------------------------------------------------------------
// Stage 1: GCN per row. One block per row, 1024 threads.
// ---------------------------------------------------------------------------
__global__ __launch_bounds__(Ndim)
void gcn_kernel(const float* __restrict__ inp,
                const float* __restrict__ w1, const float* __restrict__ b1,
                const float* __restrict__ w2, const float* __restrict__ b2)
{
    __shared__ float xs[Ndim];
    __shared__ float s2[Ndim];
    const int i   = threadIdx.x;
    const int row = blockIdx.x;

    const float xi = inp[row * Ndim + i];
    xs[i] = xi;
    __syncthreads();

    float d0 = INFINITY, d1 = INFINITY, d2 = INFINITY, d3 = INFINITY;
    int   j0 = 0, j1 = 0, j2 = 0, j3 = 0;

    #pragma unroll 4
    for (int j = 0; j < Ndim; j++) {
        float d = fabsf(xi - xs[j]);
        if (j != i && d < d3) {
            if (d < d2) {
                d3 = d2; j3 = j2;
                if (d < d1) {
                    d2 = d1; j2 = j1;
                    if (d < d0) { d1 = d0; j1 = j0; d0 = d; j0 = j; }
                    else        { d1 = d;  j1 = j; }
                } else { d2 = d; j2 = j; }
            } else { d3 = d; j3 = j; }
        }
    }

    const float S = xs[j0] + xs[j1] + xs[j2] + xs[j3];

    float acc = 0.f;
    #pragma unroll
    for (int c = 0; c < 4; c++) {
        float h = fmaxf(S * w1[c] + b1[c], 0.f);
        acc += h * w2[c];
    }
    s2[i] = acc;
    __syncthreads();

    g_gcn[row * Ndim + i] = s2[j0] + s2[j1] + s2[j2] + s2[j3] + b2[0];
}

// ---------------------------------------------------------------------------
// Stage 2a: first layer (K=1024, N=256): warp-per-output dot kernel.
// ---------------------------------------------------------------------------
__global__ __launch_bounds__(256)
void fc1_kernel(const float* __restrict__ W, const float* __restrict__ bias)
{
    const int gw   = (blockIdx.x * blockDim.x + threadIdx.x) >> 5;
    const int lane = threadIdx.x & 31;
    const int m = gw >> 8;
    const int n = gw & 255;

    const float4* ar = (const float4*)(g_gcn + m * Ndim);
    const float4* wr = (const float4*)(W     + n * Ndim);

    float a = 0.f;
    #pragma unroll
    for (int it = 0; it < 8; it++) {
        float4 av = ar[it * 32 + lane];
        float4 wv = wr[it * 32 + lane];
        a += av.x * wv.x + av.y * wv.y + av.z * wv.z + av.w * wv.w;
    }
    #pragma unroll
    for (int off = 16; off; off >>= 1)
        a += __shfl_down_sync(0xffffffffu, a, off);

    if (lane == 0)
        g_f[m * H16d + n] = fmaxf(a + bias[n], 0.f);
}

// ---------------------------------------------------------------------------
// Tiled SGEMM, M=64 rows, BN=32 cols/block, BK=32, 128 threads, 4x4 micro.
// C[m][n] = act( A[m,:K] . W[n,:K] + bias[n] (+bias2[n]) )
// ---------------------------------------------------------------------------
template<int K, bool RELU>
__global__ __launch_bounds__(128)
void gemm64x32(const float* __restrict__ A, const float* __restrict__ W,
               const float* __restrict__ bias, const float* __restrict__ bias2,
               float* __restrict__ C, int Ncols)
{
    __shared__ __align__(16) float As[32][68];
    __shared__ __align__(16) float Ws[32][36];

    const int tid = threadIdx.x;
    const int tx  = tid & 7;         // n group 0..7
    const int ty  = tid >> 3;        // m group 0..15
    const int nb  = blockIdx.x * 32;

    const int alm = tid >> 1;        // A row 0..63
    const int alk = (tid & 1) * 16;  // base k for 4 float4
    const int wln = tid >> 2;        // W row 0..31
    const int wlk = (tid & 3) * 8;   // base k for 2 float4

    float acc[4][4];
    #pragma unroll
    for (int a = 0; a < 4; a++)
        #pragma unroll
        for (int b = 0; b < 4; b++) acc[a][b] = 0.f;

    for (int kc = 0; kc < K; kc += 32) {
        #pragma unroll
        for (int i = 0; i < 4; i++) {
            float4 v = *(const float4*)(A + (size_t)alm * K + kc + alk + i * 4);
            As[alk + i*4 + 0][alm] = v.x; As[alk + i*4 + 1][alm] = v.y;
            As[alk + i*4 + 2][alm] = v.z; As[alk + i*4 + 3][alm] = v.w;
        }
        #pragma unroll
        for (int i = 0; i < 2; i++) {
            float4 v = *(const float4*)(W + (size_t)(nb + wln) * K + kc + wlk + i * 4);
            Ws[wlk + i*4 + 0][wln] = v.x; Ws[wlk + i*4 + 1][wln] = v.y;
            Ws[wlk + i*4 + 2][wln] = v.z; Ws[wlk + i*4 + 3][wln] = v.w;
        }
        __syncthreads();

        #pragma unroll
        for (int kk = 0; kk < 32; kk++) {
            float4 av = *(const float4*)&As[kk][ty * 4];
            float4 wv = *(const float4*)&Ws[kk][tx * 4];
            acc[0][0] += av.x*wv.x; acc[0][1] += av.x*wv.y; acc[0][2] += av.x*wv.z; acc[0][3] += av.x*wv.w;
            acc[1][0] += av.y*wv.x; acc[1][1] += av.y*wv.y; acc[1][2] += av.y*wv.z; acc[1][3] += av.y*wv.w;
            acc[2][0] += av.z*wv.x; acc[2][1] += av.z*wv.y; acc[2][2] += av.z*wv.z; acc[2][3] += av.z*wv.w;
            acc[3][0] += av.w*wv.x; acc[3][1] += av.w*wv.y; acc[3][2] += av.w*wv.z; acc[3][3] += av.w*wv.w;
        }
        __syncthreads();
    }

    #pragma unroll
    for (int a = 0; a < 4; a++) {
        const int m = ty * 4 + a;
        #pragma unroll
        for (int b = 0; b < 4; b++) {
            const int n = nb + tx * 4 + b;
            float v = acc[a][b] + bias[n];
            if (bias2) v += bias2[n];
            if (RELU)  v = fmaxf(v, 0.f);
            C[(size_t)m * Ncols + n] = v;
        }
    }
}

// ---------------------------------------------------------------------------
// Reset grid-barrier counter (must run before the persistent LSTM each replay)
// ---------------------------------------------------------------------------
__global__ void init_bar_kernel() { if (threadIdx.x == 0) g_bar = 0u; }

// ---------------------------------------------------------------------------
// Persistent LSTM. grid = min(#SMs, resident). Block b owns nu hidden units
// (all 4 gate rows each) -> cell state stays block-local in smem.
// First CACHED local rows of w_hh live in smem; the rest stream from L2.
// One atomic grid barrier per step. h written directly into d_out and read
// back as h_prev next step.
// ---------------------------------------------------------------------------
__global__ __launch_bounds__(1024, 1)
void lstm_persistent_kernel(const float* __restrict__ whh,
                            float* __restrict__ out)
{
    extern __shared__ __align__(16) float smem[];
    float* ws     = smem;                    // CACHED * 2048
    float* hs     = ws + CACHED * H128d;     // 2048
    float* rowacc = hs + H128d;              // 96
    float* c_s    = rowacc + 96;             // 24

    const int tid  = threadIdx.x;
    const int lane = tid & 31;
    const int warp = tid >> 5;
    const int nb   = gridDim.x;
    const int b    = blockIdx.x;

    // unit partition: first `rem` blocks get nu_base+1 units
    const int nu_base = H128d / nb;
    const int rem     = H128d - nu_base * nb;
    const int nu      = nu_base + (b < rem ? 1 : 0);
    const int u0      = b * nu_base + (b < rem ? b : rem);
    const int nrows   = 4 * nu;              // local rows: lr = uu*4 + g

    // ---- prologue: cache first CACHED local rows of w_hh in smem ----
    #pragma unroll 1
    for (int lr = 0; lr < CACHED; lr++) {
        const int uu = lr >> 2, g = lr & 3;
        const float4* src = (const float4*)(whh + ((size_t)(g * H128d + u0 + uu)) * H128d);
        float4* dst = (float4*)(ws + (size_t)lr * H128d);
        for (int i = tid; i < H128d / 4; i += 1024) dst[i] = src[i];
    }
    if (tid < nu) c_s[tid] = 0.f;

    const float4* hs4 = (const float4*)hs;

    for (int t = 0; t < Bdim; t++) {
        // ---- stage h_prev into smem ----
        if (tid < H128d / 4) {
            float4* h4 = (float4*)hs;
            if (t == 0) h4[tid] = make_float4(0.f, 0.f, 0.f, 0.f);
            else        h4[tid] = ((const float4*)(out + (size_t)(t - 1) * H128d))[tid];
        }
        __syncthreads();

        // ---- matvec: warp per row, rows strided by 32 ----
        for (int lr = warp; lr < nrows; lr += 32) {
            const int uu = lr >> 2, g = lr & 3;
            const float4* wr = (lr < CACHED)
                ? (const float4*)(ws + (size_t)lr * H128d)
                : (const float4*)(whh + ((size_t)(g * H128d + u0 + uu)) * H128d);
            float a = 0.f;
            #pragma unroll 8
            for (int i = 0; i < 16; i++) {
                float4 w4 = wr[i * 32 + lane];
                float4 h4 = hs4[i * 32 + lane];
                a = fmaf(w4.x, h4.x, a); a = fmaf(w4.y, h4.y, a);
                a = fmaf(w4.z, h4.z, a); a = fmaf(w4.w, h4.w, a);
            }
            #pragma unroll
            for (int off = 16; off; off >>= 1)
                a += __shfl_down_sync(0xffffffffu, a, off);
            if (lane == 0) rowacc[lr] = a;
        }
        __syncthreads();

        // ---- gate combine + state update (one thread per owned unit) ----
        if (tid < nu) {
            const int j = u0 + tid;
            const float* gih = g_gih + (size_t)t * G4d;
            float ig = rowacc[tid * 4 + 0] + gih[j];
            float fg = rowacc[tid * 4 + 1] + gih[H128d + j];
            float gg = rowacc[tid * 4 + 2] + gih[2 * H128d + j];
            float og = rowacc[tid * 4 + 3] + gih[3 * H128d + j];

            float si = 1.f / (1.f + __expf(-ig));
            float sf = 1.f / (1.f + __expf(-fg));
            float so = 1.f / (1.f + __expf(-og));

            float cn = sf * c_s[tid] + si * tanhf(gg);
            float hn = so * tanhf(cn);
            c_s[tid] = cn;
            out[(size_t)t * H128d + j] = hn;
        }

        // ---- grid barrier ----
        __syncthreads();
        if (tid == 0) {
            __threadfence();
            atomicAdd(&g_bar, 1u);
            const unsigned target = (unsigned)nb * (unsigned)(t + 1);
            while (*((volatile unsigned*)&g_bar) < target) __nanosleep(32);
            __threadfence();
        }
        __syncthreads();
    }
}

// ---------------------------------------------------------------------------
extern "C" void kernel_launch(void* const* d_in, const int* in_sizes, int n_in,
                              void* d_out, int out_size)
{
    const float* input = (const float*)d_in[0];
    const float* gc1_w = (const float*)d_in[3];
    const float* gc1_b = (const float*)d_in[4];
    const float* gc2_w = (const float*)d_in[5];
    const float* gc2_b = (const float*)d_in[6];
    const float* fl_w  = (const float*)d_in[7];
    const float* fl_b  = (const float*)d_in[8];
    const float* il_w  = (const float*)d_in[9];
    const float* il_b  = (const float*)d_in[10];
    const float* ol_w  = (const float*)d_in[11];
    const float* ol_b  = (const float*)d_in[12];
    const float* w_ih  = (const float*)d_in[13];
    const float* w_hh  = (const float*)d_in[14];
    const float* b_ih  = (const float*)d_in[15];
    const float* b_hh  = (const float*)d_in[16];
    float* out = (float*)d_out;

    float *p_f, *p_i, *p_z, *p_gih;
    cudaGetSymbolAddress((void**)&p_f,   g_f);
    cudaGetSymbolAddress((void**)&p_i,   g_i);
    cudaGetSymbolAddress((void**)&p_z,   g_z);
    cudaGetSymbolAddress((void**)&p_gih, g_gih);

    const int lstm_smem = (CACHED * H128d + H128d + 96 + 24) * (int)sizeof(float);
    cudaFuncSetAttribute(lstm_persistent_kernel,
                         cudaFuncAttributeMaxDynamicSharedMemorySize, lstm_smem);

    // Residency-safe persistent grid: never launch more blocks than can be
    // simultaneously resident (spin grid-barrier requires co-residency).
    int nsm = 148, per_sm = 1;
    cudaDeviceGetAttribute(&nsm, cudaDevAttrMultiProcessorCount, 0);
    cudaOccupancyMaxActiveBlocksPerMultiprocessor(&per_sm, lstm_persistent_kernel,
                                                  1024, lstm_smem);
    if (per_sm < 1) per_sm = 1;          // launch would fail loudly anyway
    int grid = nsm * (per_sm > 1 ? 1 : 1);
    if (grid > 512) grid = 512;

    // Stage 1: GCN
    gcn_kernel<<<Bdim, Ndim>>>(input, gc1_w, gc1_b, gc2_w, gc2_b);

    // Stage 2: MLP chain + input projection (biases folded, relu fused)
    fc1_kernel<<<(Bdim * H16d) / 8, 256>>>(fl_w, fl_b);
    gemm64x32<H16d,  true ><<<H64d  / 32, 128>>>(p_f, il_w, il_b, nullptr, p_i,   H64d);
    gemm64x32<H64d,  true ><<<H128d / 32, 128>>>(p_i, ol_w, ol_b, nullptr, p_z,   H128d);
    gemm64x32<H128d, false><<<G4d   / 32, 128>>>(p_z, w_ih, b_ih, b_hh,    p_gih, G4d);

    // Stage 3: persistent LSTM (all 64 steps in one kernel)
    init_bar_kernel<<<1, 32>>>();
    lstm_persistent_kernel<<<grid, 1024, lstm_smem>>>(w_hh, out);
}

// round 4
// speedup vs baseline: 1.2524x; 1.1075x over previous
#include <cuda_runtime.h>
#include <math.h>

#define Bdim   64
#define Ndim   1024
#define H16d   256
#define H64d   1024
#define H128d  2048
#define G4d    8192   // 4*H128

#define CACHED 26     // w_hh rows cached in smem per block (even: pairs never straddle)

// ---------------- scratch (device globals; no allocations allowed) ----------
__device__ float g_gcn[Bdim * Ndim];
__device__ float g_f  [Bdim * H16d];
__device__ float g_i  [Bdim * H64d];
__device__ float g_z  [Bdim * H128d];
__device__ float g_gih[Bdim * G4d];      // z@w_ih^T + b_ih + b_hh
__device__ unsigned g_bar;               // grid barrier counter

// ---------------------------------------------------------------------------
// Stage 1: GCN per row. One block per row, 1024 threads.
// ---------------------------------------------------------------------------
__global__ __launch_bounds__(Ndim)
void gcn_kernel(const float* __restrict__ inp,
                const float* __restrict__ w1, const float* __restrict__ b1,
                const float* __restrict__ w2, const float* __restrict__ b2)
{
    __shared__ float xs[Ndim];
    __shared__ float s2[Ndim];
    const int i   = threadIdx.x;
    const int row = blockIdx.x;

    const float xi = inp[row * Ndim + i];
    xs[i] = xi;
    __syncthreads();

    float d0 = INFINITY, d1 = INFINITY, d2 = INFINITY, d3 = INFINITY;
    int   j0 = 0, j1 = 0, j2 = 0, j3 = 0;

    #pragma unroll 4
    for (int j = 0; j < Ndim; j++) {
        float d = fabsf(xi - xs[j]);
        if (j != i && d < d3) {
            if (d < d2) {
                d3 = d2; j3 = j2;
                if (d < d1) {
                    d2 = d1; j2 = j1;
                    if (d < d0) { d1 = d0; j1 = j0; d0 = d; j0 = j; }
                    else        { d1 = d;  j1 = j; }
                } else { d2 = d; j2 = j; }
            } else { d3 = d; j3 = j; }
        }
    }

    const float S = xs[j0] + xs[j1] + xs[j2] + xs[j3];

    float acc = 0.f;
    #pragma unroll
    for (int c = 0; c < 4; c++) {
        float h = fmaxf(S * w1[c] + b1[c], 0.f);
        acc += h * w2[c];
    }
    s2[i] = acc;
    __syncthreads();

    g_gcn[row * Ndim + i] = s2[j0] + s2[j1] + s2[j2] + s2[j3] + b2[0];
}

// ---------------------------------------------------------------------------
// Stage 2a: first layer (K=1024, N=256): warp-per-output dot kernel.
// ---------------------------------------------------------------------------
__global__ __launch_bounds__(256)
void fc1_kernel(const float* __restrict__ W, const float* __restrict__ bias)
{
    const int gw   = (blockIdx.x * blockDim.x + threadIdx.x) >> 5;
    const int lane = threadIdx.x & 31;
    const int m = gw >> 8;
    const int n = gw & 255;

    const float4* ar = (const float4*)(g_gcn + m * Ndim);
    const float4* wr = (const float4*)(W     + n * Ndim);

    float a = 0.f;
    #pragma unroll
    for (int it = 0; it < 8; it++) {
        float4 av = ar[it * 32 + lane];
        float4 wv = wr[it * 32 + lane];
        a += av.x * wv.x + av.y * wv.y + av.z * wv.z + av.w * wv.w;
    }
    #pragma unroll
    for (int off = 16; off; off >>= 1)
        a += __shfl_down_sync(0xffffffffu, a, off);

    if (lane == 0)
        g_f[m * H16d + n] = fmaxf(a + bias[n], 0.f);
}

// ---------------------------------------------------------------------------
// Stage 2b: tiled SGEMM v2. M=64 rows, BN=32 cols/block, BK=32.
// 256 threads (8 warps), double-buffered smem tiles, register prefetch,
// one __syncthreads per K-tile. Micro-tile 2x4 per thread.
// C[m][n] = act( A[m,:K] . W[n,:K] + bias[n] (+bias2[n]) )
// ---------------------------------------------------------------------------
template<int K, bool RELU>
__global__ __launch_bounds__(256)
void gemm_v2(const float* __restrict__ A, const float* __restrict__ W,
             const float* __restrict__ bias, const float* __restrict__ bias2,
             float* __restrict__ C, int Ncols)
{
    __shared__ __align__(16) float As[2][32][66];  // [k][m], stride 66
    __shared__ __align__(16) float Ws[2][32][34];  // [k][n], stride 34

    const int tid = threadIdx.x;
    const int tx  = tid & 7;         // n group: 4 cols
    const int ty  = tid >> 3;        // m group: 2 rows (0..31)
    const int nb  = blockIdx.x * 32;

    const int lr = tid >> 3;         // loader row 0..31
    const int lk = tid & 7;          // loader k-float4 0..7

    const int NT = K / 32;

    float4 rA0, rA1, rW;

    // prologue: load tile 0
    rA0 = *(const float4*)(A + (size_t)lr        * K + lk * 4);
    rA1 = *(const float4*)(A + (size_t)(lr + 32) * K + lk * 4);
    rW  = *(const float4*)(W + (size_t)(nb + lr) * K + lk * 4);
    {
        const int k4 = lk * 4;
        As[0][k4+0][lr] = rA0.x; As[0][k4+1][lr] = rA0.y;
        As[0][k4+2][lr] = rA0.z; As[0][k4+3][lr] = rA0.w;
        As[0][k4+0][lr+32] = rA1.x; As[0][k4+1][lr+32] = rA1.y;
        As[0][k4+2][lr+32] = rA1.z; As[0][k4+3][lr+32] = rA1.w;
        Ws[0][k4+0][lr] = rW.x; Ws[0][k4+1][lr] = rW.y;
        Ws[0][k4+2][lr] = rW.z; Ws[0][k4+3][lr] = rW.w;
    }
    __syncthreads();

    float acc[2][4];
    #pragma unroll
    for (int a = 0; a < 2; a++)
        #pragma unroll
        for (int b = 0; b < 4; b++) acc[a][b] = 0.f;

    for (int t = 0; t < NT; t++) {
        const int cur = t & 1;
        if (t + 1 < NT) {
            const int kc = (t + 1) * 32;
            rA0 = *(const float4*)(A + (size_t)lr        * K + kc + lk * 4);
            rA1 = *(const float4*)(A + (size_t)(lr + 32) * K + kc + lk * 4);
            rW  = *(const float4*)(W + (size_t)(nb + lr) * K + kc + lk * 4);
        }

        #pragma unroll
        for (int kk = 0; kk < 32; kk++) {
            float2 a01 = *(const float2*)&As[cur][kk][ty * 2];
            float2 w01 = *(const float2*)&Ws[cur][kk][tx * 4];
            float2 w23 = *(const float2*)&Ws[cur][kk][tx * 4 + 2];
            acc[0][0] = fmaf(a01.x, w01.x, acc[0][0]);
            acc[0][1] = fmaf(a01.x, w01.y, acc[0][1]);
            acc[0][2] = fmaf(a01.x, w23.x, acc[0][2]);
            acc[0][3] = fmaf(a01.x, w23.y, acc[0][3]);
            acc[1][0] = fmaf(a01.y, w01.x, acc[1][0]);
            acc[1][1] = fmaf(a01.y, w01.y, acc[1][1]);
            acc[1][2] = fmaf(a01.y, w23.x, acc[1][2]);
            acc[1][3] = fmaf(a01.y, w23.y, acc[1][3]);
        }

        if (t + 1 < NT) {
            const int nxt = (t + 1) & 1;
            const int k4 = lk * 4;
            As[nxt][k4+0][lr] = rA0.x; As[nxt][k4+1][lr] = rA0.y;
            As[nxt][k4+2][lr] = rA0.z; As[nxt][k4+3][lr] = rA0.w;
            As[nxt][k4+0][lr+32] = rA1.x; As[nxt][k4+1][lr+32] = rA1.y;
            As[nxt][k4+2][lr+32] = rA1.z; As[nxt][k4+3][lr+32] = rA1.w;
            Ws[nxt][k4+0][lr] = rW.x; Ws[nxt][k4+1][lr] = rW.y;
            Ws[nxt][k4+2][lr] = rW.z; Ws[nxt][k4+3][lr] = rW.w;
        }
        __syncthreads();
    }

    #pragma unroll
    for (int a = 0; a < 2; a++) {
        const int m = ty * 2 + a;
        #pragma unroll
        for (int b = 0; b < 4; b++) {
            const int n = nb + tx * 4 + b;
            float v = acc[a][b] + bias[n];
            if (bias2) v += bias2[n];
            if (RELU)  v = fmaxf(v, 0.f);
            C[(size_t)m * Ncols + n] = v;
        }
    }
}

// ---------------------------------------------------------------------------
__global__ void init_bar_kernel() { if (threadIdx.x == 0) g_bar = 0u; }

// ---------------------------------------------------------------------------
// Persistent LSTM v2. Block b owns nu hidden units (all 4 gate rows each).
// Warp w handles local rows 2w, 2w+1 INTERLEAVED (one h read serves both),
// 4 independent FMA accumulators. First CACHED rows in smem, rest from L2.
// ---------------------------------------------------------------------------
__global__ __launch_bounds__(1024, 1)
void lstm_persistent_kernel(const float* __restrict__ whh,
                            float* __restrict__ out)
{
    extern __shared__ __align__(16) float smem[];
    float* ws     = smem;                      // CACHED * 2048
    float* hs     = ws + CACHED * H128d;       // 2048
    float* rowacc = hs + H128d;                // 64
    float* c_s    = rowacc + 64;               // 16

    const int tid  = threadIdx.x;
    const int lane = tid & 31;
    const int warp = tid >> 5;
    const int nb   = gridDim.x;
    const int b    = blockIdx.x;

    const int nu_base = H128d / nb;
    const int rem     = H128d - nu_base * nb;
    const int nu      = nu_base + (b < rem ? 1 : 0);
    const int u0      = b * nu_base + (b < rem ? b : rem);
    const int nrows   = 4 * nu;                // multiple of 4 -> even

    // ---- prologue: cache first CACHED local rows of w_hh in smem ----
    #pragma unroll 1
    for (int lr = 0; lr < CACHED; lr++) {
        const int uu = lr >> 2, g = lr & 3;
        const float4* src = (const float4*)(whh + ((size_t)(g * H128d + u0 + uu)) * H128d);
        float4* dst = (float4*)(ws + (size_t)lr * H128d);
        for (int i = tid; i < H128d / 4; i += 1024) dst[i] = src[i];
    }
    if (tid < nu) c_s[tid] = 0.f;

    const float4* hs4 = (const float4*)hs;
    const int r0 = warp * 2;
    const int r1 = r0 + 1;

    for (int t = 0; t < Bdim; t++) {
        // ---- stage h_prev into smem ----
        if (tid < H128d / 4) {
            float4* h4 = (float4*)hs;
            if (t == 0) h4[tid] = make_float4(0.f, 0.f, 0.f, 0.f);
            else        h4[tid] = ((const float4*)(out + (size_t)(t - 1) * H128d))[tid];
        }
        __syncthreads();

        // ---- matvec: warp handles rows r0, r1 interleaved ----
        if (r0 < nrows) {
            float a0 = 0.f, b0 = 0.f, a1 = 0.f, b1 = 0.f;
            if (r0 < CACHED) {
                const float4* w0 = (const float4*)(ws + (size_t)r0 * H128d);
                const float4* w1 = (const float4*)(ws + (size_t)r1 * H128d);
                #pragma unroll
                for (int i = 0; i < 16; i += 2) {
                    float4 h0 = hs4[i * 32 + lane];
                    float4 h1 = hs4[(i + 1) * 32 + lane];
                    float4 x0 = w0[i * 32 + lane];
                    float4 x1 = w0[(i + 1) * 32 + lane];
                    float4 y0 = w1[i * 32 + lane];
                    float4 y1 = w1[(i + 1) * 32 + lane];
                    a0 = fmaf(x0.x,h0.x,a0); a0 = fmaf(x0.y,h0.y,a0); a0 = fmaf(x0.z,h0.z,a0); a0 = fmaf(x0.w,h0.w,a0);
                    b0 = fmaf(x1.x,h1.x,b0); b0 = fmaf(x1.y,h1.y,b0); b0 = fmaf(x1.z,h1.z,b0); b0 = fmaf(x1.w,h1.w,b0);
                    a1 = fmaf(y0.x,h0.x,a1); a1 = fmaf(y0.y,h0.y,a1); a1 = fmaf(y0.z,h0.z,a1); a1 = fmaf(y0.w,h0.w,a1);
                    b1 = fmaf(y1.x,h1.x,b1); b1 = fmaf(y1.y,h1.y,b1); b1 = fmaf(y1.z,h1.z,b1); b1 = fmaf(y1.w,h1.w,b1);
                }
            } else {
                const int uu0 = r0 >> 2, g0 = r0 & 3;
                const int uu1 = r1 >> 2, g1 = r1 & 3;
                const float4* w0 = (const float4*)(whh + ((size_t)(g0 * H128d + u0 + uu0)) * H128d);
                const float4* w1 = (const float4*)(whh + ((size_t)(g1 * H128d + u0 + uu1)) * H128d);
                #pragma unroll
                for (int i = 0; i < 16; i += 2) {
                    float4 x0 = w0[i * 32 + lane];
                    float4 x1 = w0[(i + 1) * 32 + lane];
                    float4 y0 = w1[i * 32 + lane];
                    float4 y1 = w1[(i + 1) * 32 + lane];
                    float4 h0 = hs4[i * 32 + lane];
                    float4 h1 = hs4[(i + 1) * 32 + lane];
                    a0 = fmaf(x0.x,h0.x,a0); a0 = fmaf(x0.y,h0.y,a0); a0 = fmaf(x0.z,h0.z,a0); a0 = fmaf(x0.w,h0.w,a0);
                    b0 = fmaf(x1.x,h1.x,b0); b0 = fmaf(x1.y,h1.y,b0); b0 = fmaf(x1.z,h1.z,b0); b0 = fmaf(x1.w,h1.w,b0);
                    a1 = fmaf(y0.x,h0.x,a1); a1 = fmaf(y0.y,h0.y,a1); a1 = fmaf(y0.z,h0.z,a1); a1 = fmaf(y0.w,h0.w,a1);
                    b1 = fmaf(y1.x,h1.x,b1); b1 = fmaf(y1.y,h1.y,b1); b1 = fmaf(y1.z,h1.z,b1); b1 = fmaf(y1.w,h1.w,b1);
                }
            }
            a0 += b0; a1 += b1;
            #pragma unroll
            for (int off = 16; off; off >>= 1) {
                a0 += __shfl_down_sync(0xffffffffu, a0, off);
                a1 += __shfl_down_sync(0xffffffffu, a1, off);
            }
            if (lane == 0) { rowacc[r0] = a0; rowacc[r1] = a1; }
        }
        __syncthreads();

        // ---- gate combine + state update ----
        if (tid < nu) {
            const int j = u0 + tid;
            const float* gih = g_gih + (size_t)t * G4d;
            float ig = rowacc[tid * 4 + 0] + gih[j];
            float fg = rowacc[tid * 4 + 1] + gih[H128d + j];
            float gg = rowacc[tid * 4 + 2] + gih[2 * H128d + j];
            float og = rowacc[tid * 4 + 3] + gih[3 * H128d + j];

            float si = 1.f / (1.f + __expf(-ig));
            float sf = 1.f / (1.f + __expf(-fg));
            float so = 1.f / (1.f + __expf(-og));

            float cn = sf * c_s[tid] + si * tanhf(gg);
            float hn = so * tanhf(cn);
            c_s[tid] = cn;
            out[(size_t)t * H128d + j] = hn;
        }

        // ---- grid barrier ----
        __syncthreads();
        if (tid == 0) {
            __threadfence();
            atomicAdd(&g_bar, 1u);
            const unsigned target = (unsigned)nb * (unsigned)(t + 1);
            while (*((volatile unsigned*)&g_bar) < target) __nanosleep(20);
            __threadfence();
        }
        __syncthreads();
    }
}

// ---------------------------------------------------------------------------
extern "C" void kernel_launch(void* const* d_in, const int* in_sizes, int n_in,
                              void* d_out, int out_size)
{
    const float* input = (const float*)d_in[0];
    const float* gc1_w = (const float*)d_in[3];
    const float* gc1_b = (const float*)d_in[4];
    const float* gc2_w = (const float*)d_in[5];
    const float* gc2_b = (const float*)d_in[6];
    const float* fl_w  = (const float*)d_in[7];
    const float* fl_b  = (const float*)d_in[8];
    const float* il_w  = (const float*)d_in[9];
    const float* il_b  = (const float*)d_in[10];
    const float* ol_w  = (const float*)d_in[11];
    const float* ol_b  = (const float*)d_in[12];
    const float* w_ih  = (const float*)d_in[13];
    const float* w_hh  = (const float*)d_in[14];
    const float* b_ih  = (const float*)d_in[15];
    const float* b_hh  = (const float*)d_in[16];
    float* out = (float*)d_out;

    float *p_f, *p_i, *p_z, *p_gih;
    cudaGetSymbolAddress((void**)&p_f,   g_f);
    cudaGetSymbolAddress((void**)&p_i,   g_i);
    cudaGetSymbolAddress((void**)&p_z,   g_z);
    cudaGetSymbolAddress((void**)&p_gih, g_gih);

    const int lstm_smem = (CACHED * H128d + H128d + 64 + 16) * (int)sizeof(float);
    cudaFuncSetAttribute(lstm_persistent_kernel,
                         cudaFuncAttributeMaxDynamicSharedMemorySize, lstm_smem);

    int nsm = 148;
    cudaDeviceGetAttribute(&nsm, cudaDevAttrMultiProcessorCount, 0);
    int grid = nsm;
    if (grid > 512) grid = 512;

    // Stage 1: GCN
    gcn_kernel<<<Bdim, Ndim>>>(input, gc1_w, gc1_b, gc2_w, gc2_b);

    // Stage 2: MLP chain + input projection
    fc1_kernel<<<(Bdim * H16d) / 8, 256>>>(fl_w, fl_b);
    gemm_v2<H16d,  true ><<<H64d  / 32, 256>>>(p_f, il_w, il_b, nullptr, p_i,   H64d);
    gemm_v2<H64d,  true ><<<H128d / 32, 256>>>(p_i, ol_w, ol_b, nullptr, p_z,   H128d);
    gemm_v2<H128d, false><<<G4d   / 32, 256>>>(p_z, w_ih, b_ih, b_hh,    p_gih, G4d);

    // Stage 3: persistent LSTM
    init_bar_kernel<<<1, 32>>>();
    lstm_persistent_kernel<<<grid, 1024, lstm_smem>>>(w_hh, out);
}